// round 9
// baseline (speedup 1.0000x reference)
#include <cuda_runtime.h>
#include <math_constants.h>

#define BB   16
#define NN   2048
#define KNB  20
#define BN   (BB*NN)        // 32768
#define PTS  32
#define NBLK (BN/PTS)       // 1024
#define CCAT 512

// ---------------- scratch (device globals; no allocation allowed) ----------
__device__ int   g_idx [BN*KNB];
__device__ float g_hcat[BN*CCAT];
__device__ float g_pre [BN*256];
__device__ float g_part[NBLK*256*2];
__device__ float g_mean[256];
__device__ float g_rstd[256];

__global__ void nop_kernel() {}

// ---------------- kNN: EXACT top-20, split-scan (2 threads/query) ----------
// Each lane pair (2q, 2q+1) splits the 2048 candidates; each keeps an exact
// sorted top-20; merged with the bitonic top-k identity:
//   top20(A u B) = { max(A[k], B[19-k]) }  for desc-sorted A, B.
__global__ void __launch_bounds__(256) knn_kernel(const float* __restrict__ x)
{
    __shared__ float4 sp[NN];                // (x, y, z, |p|^2)
    const int b = blockIdx.y;
    const float* xb = x + (size_t)b*NN*3;
    for (int i = threadIdx.x; i < NN; i += 256) {
        float a0 = xb[i*3], a1 = xb[i*3+1], a2 = xb[i*3+2];
        sp[i] = make_float4(a0, a1, a2, a0*a0 + a1*a1 + a2*a2);
    }
    __syncthreads();
    const int t = threadIdx.x;
    const int q = t >> 1, h = t & 1;         // query, half
    const int n = blockIdx.x*128 + q;
    const float4 qv = sp[n];

    float bv[KNB]; int bi[KNB];
    #pragma unroll
    for (int j = 0; j < KNB; ++j) { bv[j] = -CUDART_INF_F; bi[j] = 0; }

    const int mbase = h*1024;
    #pragma unroll 4
    for (int ml = 0; ml < 1024; ++ml) {
        const int m = mbase + ml;
        float4 pm = sp[m];
        float v = 2.f*(qv.x*pm.x + qv.y*pm.y + qv.z*pm.z) - qv.w - pm.w;
        if (v > bv[KNB-1]) {
            #pragma unroll
            for (int j = KNB-1; j >= 1; --j) {
                bool shift = v > bv[j-1];
                float nv = shift ? bv[j-1] : v;
                int   ni = shift ? bi[j-1] : m;
                if (v > bv[j]) { bv[j] = nv; bi[j] = ni; }
            }
            if (v > bv[0]) { bv[0] = v; bi[0] = m; }
        }
    }

    // exchange lists within the lane pair
    float pv[KNB]; int pi[KNB];
    #pragma unroll
    for (int j = 0; j < KNB; ++j) {
        pv[j] = __shfl_xor_sync(0xffffffffu, bv[j], 1);
        pi[j] = __shfl_xor_sync(0xffffffffu, bi[j], 1);
    }
    if (h == 0) {                            // own = half0 (lower indices)
        int* out = g_idx + ((size_t)b*NN + n)*KNB;
        #pragma unroll
        for (int k = 0; k < KNB; ++k) {
            bool ta = bv[k] >= pv[KNB-1-k];  // ties -> lower index (half 0)
            out[k] = ta ? bi[k] : pi[KNB-1-k];
        }
    }
}

// ---------------- EdgeConv: pre-BN max over k + BN partial sums ------------
__global__ void __launch_bounds__(64) edge_kernel(const float* __restrict__ x,
                                                  const float* __restrict__ w_edge)
{
    __shared__ float s_nb[PTS][KNB][3];
    __shared__ float s_ctr[PTS][3];
    const int p0 = blockIdx.x * PTS;
    const int tid = threadIdx.x;

    for (int j = tid; j < PTS*KNB; j += 64) {
        int p = j / KNB, k = j - p*KNB;
        int gp = p0 + p;
        int bb = gp >> 11;
        int gi = g_idx[gp*KNB + k];
        const float* xp = x + ((size_t)bb*NN + gi)*3;
        s_nb[p][k][0] = xp[0]; s_nb[p][k][1] = xp[1]; s_nb[p][k][2] = xp[2];
    }
    if (tid < PTS) {
        int gp = p0 + tid;
        s_ctr[tid][0] = x[gp*3]; s_ctr[tid][1] = x[gp*3+1]; s_ctr[tid][2] = x[gp*3+2];
    }
    __syncthreads();

    const int o = tid;
    const float w0 = w_edge[o*6+0], w1 = w_edge[o*6+1], w2 = w_edge[o*6+2];
    const float w3 = w_edge[o*6+3], w4 = w_edge[o*6+4], w5 = w_edge[o*6+5];
    float s = 0.f, s2 = 0.f;
    for (int p = 0; p < PTS; ++p) {
        float c0 = s_ctr[p][0], c1 = s_ctr[p][1], c2 = s_ctr[p][2];
        float base = w3*c0 + w4*c1 + w5*c2;
        float mx = -CUDART_INF_F;
        #pragma unroll
        for (int k = 0; k < KNB; ++k) {
            float v = base + w0*(s_nb[p][k][0]-c0)
                           + w1*(s_nb[p][k][1]-c1)
                           + w2*(s_nb[p][k][2]-c2);
            mx = fmaxf(mx, v);
            s += v; s2 += v*v;
        }
        g_pre[(size_t)(p0+p)*64 + o] = mx;
    }
    g_part[(size_t)blockIdx.x*128 + o*2]     = s;
    g_part[(size_t)blockIdx.x*128 + o*2 + 1] = s2;
}

// ---------------- BN statistics finalize (1 block per channel) -------------
__global__ void __launch_bounds__(256) stats_kernel(int O, float inv_count)
{
    __shared__ float rs[256], rs2[256];
    const int o = blockIdx.x;
    const int t = threadIdx.x;
    float s = 0.f, s2 = 0.f;
    for (int bk = t; bk < NBLK; bk += 256) {
        s  += g_part[(size_t)bk*O*2 + o*2];
        s2 += g_part[(size_t)bk*O*2 + o*2 + 1];
    }
    rs[t] = s; rs2[t] = s2;
    __syncthreads();
    for (int w = 128; w >= 1; w >>= 1) {
        if (t < w) { rs[t] += rs[t+w]; rs2[t] += rs2[t+w]; }
        __syncthreads();
    }
    if (t == 0) {
        float m   = rs[0]  * inv_count;
        float var = rs2[0] * inv_count - m*m;
        g_mean[o] = m;
        g_rstd[o] = rsqrtf(var + 1e-5f);
    }
}

// ---------------- BN + LeakyReLU apply (vectorized x4) ---------------------
__global__ void __launch_bounds__(256) apply_kernel(int O, int off)
{
    int i4 = blockIdx.x*256 + threadIdx.x;
    int i = i4*4;
    int p = i / O, o = i - p*O;
    float4 v = *reinterpret_cast<const float4*>(&g_pre[i]);
    v.x = (v.x - g_mean[o  ]) * g_rstd[o  ];
    v.y = (v.y - g_mean[o+1]) * g_rstd[o+1];
    v.z = (v.z - g_mean[o+2]) * g_rstd[o+2];
    v.w = (v.w - g_mean[o+3]) * g_rstd[o+3];
    v.x = v.x > 0.f ? v.x : 0.2f*v.x;
    v.y = v.y > 0.f ? v.y : 0.2f*v.y;
    v.z = v.z > 0.f ? v.z : 0.2f*v.z;
    v.w = v.w > 0.f ? v.w : 0.2f*v.w;
    *reinterpret_cast<float4*>(&g_hcat[(size_t)p*CCAT + off + o]) = v;
}

// ---------------- graph-max-pool gather + 1x1 conv + BN partials -----------
template<int CIN, int COUT>
__global__ void __launch_bounds__(128) layer_kernel(const float* __restrict__ w, int off_in)
{
    __shared__ float s_g[PTS*CIN];
    __shared__ int   s_idx[PTS*KNB];
    __shared__ float xs[128], xs2[128];
    const int tid = threadIdx.x;
    const int p0  = blockIdx.x * PTS;
    constexpr int C8 = CIN/8;

    for (int j = tid; j < PTS*KNB; j += 128) s_idx[j] = g_idx[(size_t)p0*KNB + j];
    __syncthreads();

    for (int v8 = tid; v8 < PTS*C8; v8 += 128) {
        int p = v8 / C8, c8 = (v8 - p*C8)*8;
        int gp = p0 + p, bb = gp >> 11;
        const float4* hb = reinterpret_cast<const float4*>(
            g_hcat + (size_t)bb*NN*CCAT + off_in + c8);
        float4 m0 = make_float4(-CUDART_INF_F,-CUDART_INF_F,-CUDART_INF_F,-CUDART_INF_F);
        float4 m1 = m0;
        #pragma unroll
        for (int j = 0; j < KNB; ++j) {
            size_t base = (size_t)s_idx[p*KNB+j]*(CCAT/4);
            float4 t0 = hb[base], t1 = hb[base+1];
            m0.x = fmaxf(m0.x, t0.x); m0.y = fmaxf(m0.y, t0.y);
            m0.z = fmaxf(m0.z, t0.z); m0.w = fmaxf(m0.w, t0.w);
            m1.x = fmaxf(m1.x, t1.x); m1.y = fmaxf(m1.y, t1.y);
            m1.z = fmaxf(m1.z, t1.z); m1.w = fmaxf(m1.w, t1.w);
        }
        *reinterpret_cast<float4*>(&s_g[p*CIN + c8])     = m0;
        *reinterpret_cast<float4*>(&s_g[p*CIN + c8 + 4]) = m1;
    }
    __syncthreads();

    constexpr int REP  = (COUT + 127)/128;
    constexpr int SEG  = (COUT >= 128) ? 1 : (128/COUT);
    constexpr int PSEG = PTS/SEG;
    const int o  = (COUT >= 128) ? tid : (tid & (COUT-1));
    const int sg = (COUT >= 128) ? 0   : (tid / COUT);
    const int pb = sg * PSEG;

    float acc[REP][PSEG];
    #pragma unroll
    for (int r = 0; r < REP; ++r)
        #pragma unroll
        for (int p = 0; p < PSEG; ++p) acc[r][p] = 0.f;

    for (int c = 0; c < CIN; ++c) {
        float wv[REP];
        #pragma unroll
        for (int r = 0; r < REP; ++r) wv[r] = w[(o + r*128)*CIN + c];
        #pragma unroll
        for (int p = 0; p < PSEG; ++p) {
            float sv = s_g[(pb + p)*CIN + c];
            #pragma unroll
            for (int r = 0; r < REP; ++r) acc[r][p] += wv[r]*sv;
        }
    }

    float s[REP], s2[REP];
    #pragma unroll
    for (int r = 0; r < REP; ++r) {
        s[r] = 0.f; s2[r] = 0.f;
        #pragma unroll
        for (int p = 0; p < PSEG; ++p) {
            float vv = acc[r][p];
            g_pre[(size_t)(p0 + pb + p)*COUT + o + r*128] = vv;
            s[r] += vv; s2[r] += vv*vv;
        }
    }
    if (SEG == 2) {
        if (sg == 1) { xs[o] = s[0]; xs2[o] = s2[0]; }
        __syncthreads();
        if (sg == 0) { s[0] += xs[o]; s2[0] += xs2[o]; }
    }
    if (sg == 0) {
        #pragma unroll
        for (int r = 0; r < REP; ++r) {
            g_part[(size_t)blockIdx.x*COUT*2 + (o + r*128)*2]     = s[r];
            g_part[(size_t)blockIdx.x*COUT*2 + (o + r*128)*2 + 1] = s2[r];
        }
    }
}

// ---------------- final 512->1024 GEMM (tf32 MMA, frag-major smem) ---------
__device__ __forceinline__ int fkey(float f) {
    int b = __float_as_int(f);
    return b >= 0 ? b : (b ^ 0x7FFFFFFF);
}

__global__ void out_init(int* ok) {
    ok[blockIdx.x*256 + threadIdx.x] = fkey(-CUDART_INF_F);
}

__device__ __forceinline__ float cvtf_tf32(float x) {
    unsigned u;
    asm("cvt.rna.tf32.f32 %0, %1;" : "=r"(u) : "f"(x));
    return __uint_as_float(u);
}

// Fragment-major smem layouts (per 128x32 tile, 4096 floats, conflict-free):
//  A(r,k): rb=r>>4, g=r&7, s=(r>>3)&1; tig=k&3, hh=(k>>2)&1, k8=k>>3
//    addr = (rb*4 + (g>>1))*128 + k8*32 + ((g&1)*4 + tig)*4 + hh*2 + s
//  B(c,k): cb=c>>3, g=c&7
//    addr = (cb*2 + (g>>2))*128 + k8*32 + ((g&3)*4 + tig)*2 + hh
#define TILE_F 4096
#define FSMEM_BYTES (4*TILE_F*4)   // A0,B0,A1,B1

__global__ void __launch_bounds__(256, 1) final_kernel(const float* __restrict__ wf,
                                                       const float* __restrict__ bf,
                                                       int* __restrict__ okeys)
{
    extern __shared__ float smem_f[];
    float* sAb[2] = { smem_f,            smem_f + 2*TILE_F };
    float* sBb[2] = { smem_f + TILE_F,   smem_f + 3*TILE_F };
    __shared__ float sred[8][32];

    const int tid  = threadIdx.x;
    const int lane = tid & 31, w = tid >> 5;
    const int g = lane >> 2, tig = lane & 3;
    const int wm = w & 1, wn = w >> 1;
    const int b = blockIdx.z, n0 = blockIdx.x*128, o0 = blockIdx.y*128;
    const float* Ab = g_hcat + ((size_t)b*NN + n0)*CCAT;
    const float* Bw = wf + (size_t)o0*CCAT;

    float acc[4][4][4];
    #pragma unroll
    for (int mi = 0; mi < 4; ++mi)
        #pragma unroll
        for (int ni = 0; ni < 4; ++ni)
            #pragma unroll
            for (int j = 0; j < 4; ++j) acc[mi][ni][j] = 0.f;

    const int srow = tid >> 3;         // 0..31
    const int skq  = (tid & 7) * 4;    // 0,4,...,28
    const int sk8  = skq >> 3;         // staged k8 group
    const int shh  = (skq >> 2) & 1;   // staged k-half within k8

    // per-it staging bases (r = srow + it*32; c likewise)
    int abase[4], bbase[4];
    #pragma unroll
    for (int it = 0; it < 4; ++it) {
        int r  = srow + it*32;
        int rb = r >> 4, ag = r & 7, s = (r >> 3) & 1;
        abase[it] = (rb*4 + (ag>>1))*128 + sk8*32 + (ag&1)*16 + shh*2 + s;
        int cb = r >> 3, bg = r & 7;
        bbase[it] = (cb*2 + (bg>>2))*128 + sk8*32 + (bg&3)*8 + shh;
    }

    float4 ra[4], rb4[4];
    #define LDTILE(k0)                                                              \
        { _Pragma("unroll") for (int it = 0; it < 4; ++it)                          \
            ra[it] = *reinterpret_cast<const float4*>(                              \
                &Ab[(size_t)(srow + it*32)*CCAT + (k0) + skq]);                     \
          _Pragma("unroll") for (int it = 0; it < 4; ++it)                          \
            rb4[it] = *reinterpret_cast<const float4*>(                             \
                &Bw[(size_t)(srow + it*32)*CCAT + (k0) + skq]); }
    #define STTILE(buf)                                                             \
        { _Pragma("unroll") for (int it = 0; it < 4; ++it) {                        \
            float* d = sAb[buf] + abase[it];                                        \
            d[0]  = cvtf_tf32(ra[it].x);  d[4]  = cvtf_tf32(ra[it].y);              \
            d[8]  = cvtf_tf32(ra[it].z);  d[12] = cvtf_tf32(ra[it].w); }            \
          _Pragma("unroll") for (int it = 0; it < 4; ++it) {                        \
            float* d = sBb[buf] + bbase[it];                                        \
            d[0]  = cvtf_tf32(rb4[it].x); d[2]  = cvtf_tf32(rb4[it].y);             \
            d[4]  = cvtf_tf32(rb4[it].z); d[6]  = cvtf_tf32(rb4[it].w); } }

    LDTILE(0); STTILE(0);
    __syncthreads();

    for (int t = 0; t < 16; ++t) {
        const int cur = t & 1;
        if (t < 15) LDTILE((t+1)*32);
        const float* cA = sAb[cur];
        const float* cB = sBb[cur];
        #pragma unroll
        for (int k8 = 0; k8 < 4; ++k8) {
            float4 af[4];
            #pragma unroll
            for (int mi = 0; mi < 4; ++mi) {
                int rbid = wm*4 + mi;
                af[mi] = *reinterpret_cast<const float4*>(
                    &cA[(rbid*4 + (g>>1))*128 + k8*32 + ((g&1)*4 + tig)*4]);
            }
            float2 bft[4];
            #pragma unroll
            for (int ni = 0; ni < 4; ++ni) {
                int cbid = wn*4 + ni;
                bft[ni] = *reinterpret_cast<const float2*>(
                    &cB[(cbid*2 + (g>>2))*128 + k8*32 + ((g&3)*4 + tig)*2]);
            }
            #pragma unroll
            for (int mi = 0; mi < 4; ++mi)
                #pragma unroll
                for (int ni = 0; ni < 4; ++ni) {
                    float* c = acc[mi][ni];
                    asm("mma.sync.aligned.m16n8k8.row.col.f32.tf32.tf32.f32 "
                        "{%0,%1,%2,%3}, {%4,%5,%6,%7}, {%8,%9}, {%0,%1,%2,%3};"
                        : "+f"(c[0]), "+f"(c[1]), "+f"(c[2]), "+f"(c[3])
                        : "r"(__float_as_uint(af[mi].x)), "r"(__float_as_uint(af[mi].y)),
                          "r"(__float_as_uint(af[mi].z)), "r"(__float_as_uint(af[mi].w)),
                          "r"(__float_as_uint(bft[ni].x)), "r"(__float_as_uint(bft[ni].y)));
                }
        }
        if (t < 15) STTILE((t+1) & 1);
        __syncthreads();
    }

    #pragma unroll
    for (int ni = 0; ni < 4; ++ni) {
        float m0 = -CUDART_INF_F, m1 = -CUDART_INF_F;
        #pragma unroll
        for (int mi = 0; mi < 4; ++mi) {
            m0 = fmaxf(m0, fmaxf(acc[mi][ni][0], acc[mi][ni][2]));
            m1 = fmaxf(m1, fmaxf(acc[mi][ni][1], acc[mi][ni][3]));
        }
        #pragma unroll
        for (int sh = 4; sh <= 16; sh <<= 1) {
            m0 = fmaxf(m0, __shfl_xor_sync(0xffffffffu, m0, sh));
            m1 = fmaxf(m1, __shfl_xor_sync(0xffffffffu, m1, sh));
        }
        if (g == 0) {
            sred[w][ni*8 + tig*2]     = m0;
            sred[w][ni*8 + tig*2 + 1] = m1;
        }
    }
    __syncthreads();
    if (tid < 128) {
        int cwn = tid >> 5, c = tid & 31;
        float m = fmaxf(sred[cwn*2][c], sred[cwn*2+1][c]);
        int oc = o0 + cwn*32 + c;
        m += bf[oc];
        atomicMax(&okeys[b*1024 + oc], fkey(m));
    }
}

__global__ void out_convert(int* ok, float* out) {
    int i = blockIdx.x*256 + threadIdx.x;
    int k = ok[i];
    int bits = k >= 0 ? k : (k ^ 0x7FFFFFFF);
    out[i] = __int_as_float(bits);
}

// ---------------- launch ----------------------------------------------------
extern "C" void kernel_launch(void* const* d_in, const int* in_sizes, int n_in,
                              void* d_out, int out_size)
{
    const float* x      = (const float*)d_in[0];
    const float* w_edge = (const float*)d_in[1];
    const float* w1     = (const float*)d_in[3];
    const float* w2     = (const float*)d_in[5];
    const float* w3     = (const float*)d_in[7];
    const float* wf     = (const float*)d_in[9];
    const float* bf     = (const float*)d_in[10];

    cudaFuncSetAttribute(final_kernel,
                         cudaFuncAttributeMaxDynamicSharedMemorySize, FSMEM_BYTES);

    // slots 0-2 are fillers so the ncu capture (launch index 3) hits knn
    out_init<<<out_size/256, 256>>>((int*)d_out);
    nop_kernel<<<1, 32>>>();
    nop_kernel<<<1, 32>>>();

    knn_kernel<<<dim3(NN/128, BB), 256>>>(x);

    edge_kernel<<<NBLK, 64>>>(x, w_edge);
    stats_kernel<<<64, 256>>>(64, 1.f/(float)(BN*KNB));
    apply_kernel<<<BN*64/1024, 256>>>(64, 0);

    layer_kernel<64,64><<<NBLK, 128>>>(w1, 0);
    stats_kernel<<<64, 256>>>(64, 1.f/(float)BN);
    apply_kernel<<<BN*64/1024, 256>>>(64, 64);

    layer_kernel<64,128><<<NBLK, 128>>>(w2, 64);
    stats_kernel<<<128, 256>>>(128, 1.f/(float)BN);
    apply_kernel<<<BN*128/1024, 256>>>(128, 128);

    layer_kernel<128,256><<<NBLK, 128>>>(w3, 128);
    stats_kernel<<<256, 256>>>(256, 1.f/(float)BN);
    apply_kernel<<<BN*256/1024, 256>>>(256, 256);

    final_kernel<<<dim3(16, 8, 16), 256, FSMEM_BYTES>>>(wf, bf, (int*)d_out);
    out_convert<<<out_size/256, 256>>>((int*)d_out, (float*)d_out);
}

// round 14
// speedup vs baseline: 1.0148x; 1.0148x over previous
#include <cuda_runtime.h>
#include <math_constants.h>

#define BB   16
#define NN   2048
#define KNB  20
#define BN   (BB*NN)        // 32768
#define PTS  32
#define NBLK (BN/PTS)       // 1024
#define CCAT 512

// ---------------- scratch (device globals; no allocation allowed) ----------
__device__ int   g_idx [BN*KNB];
__device__ float g_hcat[BN*CCAT];      // RAW pre-BN activations, concat layout
__device__ float g_part[NBLK*256*2];
__device__ float g_mean[CCAT];         // per-channel BN stats (persist all layers)
__device__ float g_rstd[CCAT];

__global__ void nop_kernel() {}

// BN + LeakyReLU (monotone; commutes with max) --------------------------------
__device__ __forceinline__ float bnl(float v, float m, float r) {
    float t = (v - m) * r;
    return t > 0.f ? t : 0.2f*t;
}

// ---------------- kNN: EXACT top-20 (known-good R8 version) -----------------
__global__ void __launch_bounds__(128) knn_kernel(const float* __restrict__ x)
{
    __shared__ float4 sp[NN];                // (x, y, z, |p|^2)
    const int b = blockIdx.y;
    const float* xb = x + (size_t)b*NN*3;
    for (int i = threadIdx.x; i < NN; i += 128) {
        float a0 = xb[i*3], a1 = xb[i*3+1], a2 = xb[i*3+2];
        sp[i] = make_float4(a0, a1, a2, a0*a0 + a1*a1 + a2*a2);
    }
    __syncthreads();
    const int n = blockIdx.x*128 + threadIdx.x;
    const float4 q = sp[n];

    float bv[KNB]; int bi[KNB];
    #pragma unroll
    for (int j = 0; j < KNB; ++j) { bv[j] = -CUDART_INF_F; bi[j] = 0; }

    #pragma unroll 4
    for (int m = 0; m < NN; ++m) {
        float4 pm = sp[m];                   // broadcast LDS.128
        float v = 2.f*(q.x*pm.x + q.y*pm.y + q.z*pm.z) - q.w - pm.w;
        if (v > bv[KNB-1]) {
            #pragma unroll
            for (int j = KNB-1; j >= 1; --j) {
                bool shift = v > bv[j-1];
                float nv = shift ? bv[j-1] : v;
                int   ni = shift ? bi[j-1] : m;
                if (v > bv[j]) { bv[j] = nv; bi[j] = ni; }
            }
            if (v > bv[0]) { bv[0] = v; bi[0] = m; }
        }
    }
    int* out = g_idx + ((size_t)b*NN + n)*KNB;
    #pragma unroll
    for (int j = 0; j < KNB; ++j) out[j] = bi[j];
}

// ---------------- EdgeConv: raw pre-BN max over k + BN partials -------------
// 128 threads: o = tid&63, point-half = tid>>6 (16 points each).
__global__ void __launch_bounds__(128) edge_kernel(const float* __restrict__ x,
                                                   const float* __restrict__ w_edge)
{
    __shared__ float s_nb[PTS][KNB][3];
    __shared__ float s_ctr[PTS][3];
    __shared__ float xs[64], xs2[64];
    const int p0 = blockIdx.x * PTS;
    const int tid = threadIdx.x;

    for (int j = tid; j < PTS*KNB; j += 128) {
        int p = j / KNB, k = j - p*KNB;
        int gp = p0 + p;
        int bb = gp >> 11;
        int gi = g_idx[gp*KNB + k];
        const float* xp = x + ((size_t)bb*NN + gi)*3;
        s_nb[p][k][0] = xp[0]; s_nb[p][k][1] = xp[1]; s_nb[p][k][2] = xp[2];
    }
    if (tid < PTS) {
        int gp = p0 + tid;
        s_ctr[tid][0] = x[gp*3]; s_ctr[tid][1] = x[gp*3+1]; s_ctr[tid][2] = x[gp*3+2];
    }
    __syncthreads();

    const int o = tid & 63;
    const int sg = tid >> 6;                 // 0 or 1
    const float w0 = w_edge[o*6+0], w1 = w_edge[o*6+1], w2 = w_edge[o*6+2];
    const float w3 = w_edge[o*6+3], w4 = w_edge[o*6+4], w5 = w_edge[o*6+5];
    float s = 0.f, s2 = 0.f;
    const int pb = sg*16;
    for (int p = pb; p < pb+16; ++p) {
        float c0 = s_ctr[p][0], c1 = s_ctr[p][1], c2 = s_ctr[p][2];
        float base = w3*c0 + w4*c1 + w5*c2;
        float mx = -CUDART_INF_F;
        #pragma unroll
        for (int k = 0; k < KNB; ++k) {
            float v = base + w0*(s_nb[p][k][0]-c0)
                           + w1*(s_nb[p][k][1]-c1)
                           + w2*(s_nb[p][k][2]-c2);
            mx = fmaxf(mx, v);
            s += v; s2 += v*v;
        }
        g_hcat[(size_t)(p0+p)*CCAT + o] = mx;   // raw pre-BN
    }
    if (sg == 1) { xs[o] = s; xs2[o] = s2; }
    __syncthreads();
    if (sg == 0) {
        g_part[(size_t)blockIdx.x*128 + o*2]     = s  + xs[o];
        g_part[(size_t)blockIdx.x*128 + o*2 + 1] = s2 + xs2[o];
    }
}

// ---------------- BN statistics finalize (1 block per channel) --------------
__global__ void __launch_bounds__(256) stats_kernel(int O, int moff, float inv_count)
{
    __shared__ float rs[256], rs2[256];
    const int o = blockIdx.x;
    const int t = threadIdx.x;
    float s = 0.f, s2 = 0.f;
    for (int bk = t; bk < NBLK; bk += 256) {
        s  += g_part[(size_t)bk*O*2 + o*2];
        s2 += g_part[(size_t)bk*O*2 + o*2 + 1];
    }
    rs[t] = s; rs2[t] = s2;
    __syncthreads();
    for (int w = 128; w >= 1; w >>= 1) {
        if (t < w) { rs[t] += rs[t+w]; rs2[t] += rs2[t+w]; }
        __syncthreads();
    }
    if (t == 0) {
        float m   = rs[0]  * inv_count;
        float var = rs2[0] * inv_count - m*m;
        g_mean[moff + o] = m;
        g_rstd[moff + o] = rsqrtf(var + 1e-5f);
    }
}

// ---------------- graph-max-pool gather (+inline BN) + conv + partials ------
template<int CIN, int COUT>
__global__ void __launch_bounds__(128) layer_kernel(const float* __restrict__ w,
                                                    int off_in, int off_out)
{
    __shared__ float s_g[PTS*CIN];
    __shared__ int   s_idx[PTS*KNB];
    __shared__ float xs[128], xs2[128];
    const int tid = threadIdx.x;
    const int p0  = blockIdx.x * PTS;
    constexpr int C8 = CIN/8;

    for (int j = tid; j < PTS*KNB; j += 128) s_idx[j] = g_idx[(size_t)p0*KNB + j];
    __syncthreads();

    // gather raw, max over k, then BN+LReLU once (monotone => exact)
    for (int v8 = tid; v8 < PTS*C8; v8 += 128) {
        int p = v8 / C8, c8 = (v8 - p*C8)*8;
        int gp = p0 + p, bb = gp >> 11;
        const float4* hb = reinterpret_cast<const float4*>(
            g_hcat + (size_t)bb*NN*CCAT + off_in + c8);
        float4 m0 = make_float4(-CUDART_INF_F,-CUDART_INF_F,-CUDART_INF_F,-CUDART_INF_F);
        float4 m1 = m0;
        #pragma unroll
        for (int j = 0; j < KNB; ++j) {
            size_t base = (size_t)s_idx[p*KNB+j]*(CCAT/4);
            float4 t0 = hb[base], t1 = hb[base+1];
            m0.x = fmaxf(m0.x, t0.x); m0.y = fmaxf(m0.y, t0.y);
            m0.z = fmaxf(m0.z, t0.z); m0.w = fmaxf(m0.w, t0.w);
            m1.x = fmaxf(m1.x, t1.x); m1.y = fmaxf(m1.y, t1.y);
            m1.z = fmaxf(m1.z, t1.z); m1.w = fmaxf(m1.w, t1.w);
        }
        int c = off_in + c8;
        m0.x = bnl(m0.x, g_mean[c  ], g_rstd[c  ]);
        m0.y = bnl(m0.y, g_mean[c+1], g_rstd[c+1]);
        m0.z = bnl(m0.z, g_mean[c+2], g_rstd[c+2]);
        m0.w = bnl(m0.w, g_mean[c+3], g_rstd[c+3]);
        m1.x = bnl(m1.x, g_mean[c+4], g_rstd[c+4]);
        m1.y = bnl(m1.y, g_mean[c+5], g_rstd[c+5]);
        m1.z = bnl(m1.z, g_mean[c+6], g_rstd[c+6]);
        m1.w = bnl(m1.w, g_mean[c+7], g_rstd[c+7]);
        *reinterpret_cast<float4*>(&s_g[p*CIN + c8])     = m0;
        *reinterpret_cast<float4*>(&s_g[p*CIN + c8 + 4]) = m1;
    }
    __syncthreads();

    constexpr int REP  = (COUT + 127)/128;
    constexpr int SEG  = (COUT >= 128) ? 1 : (128/COUT);
    constexpr int PSEG = PTS/SEG;
    const int o  = (COUT >= 128) ? tid : (tid & (COUT-1));
    const int sg = (COUT >= 128) ? 0   : (tid / COUT);
    const int pb = sg * PSEG;

    float acc[REP][PSEG];
    #pragma unroll
    for (int r = 0; r < REP; ++r)
        #pragma unroll
        for (int p = 0; p < PSEG; ++p) acc[r][p] = 0.f;

    for (int c = 0; c < CIN; ++c) {
        float wv[REP];
        #pragma unroll
        for (int r = 0; r < REP; ++r) wv[r] = w[(o + r*128)*CIN + c];
        #pragma unroll
        for (int p = 0; p < PSEG; ++p) {
            float sv = s_g[(pb + p)*CIN + c];
            #pragma unroll
            for (int r = 0; r < REP; ++r) acc[r][p] += wv[r]*sv;
        }
    }

    float s[REP], s2[REP];
    #pragma unroll
    for (int r = 0; r < REP; ++r) {
        s[r] = 0.f; s2[r] = 0.f;
        #pragma unroll
        for (int p = 0; p < PSEG; ++p) {
            float vv = acc[r][p];
            g_hcat[(size_t)(p0 + pb + p)*CCAT + off_out + o + r*128] = vv;  // raw
            s[r] += vv; s2[r] += vv*vv;
        }
    }
    if (SEG == 2) {
        if (sg == 1) { xs[o] = s[0]; xs2[o] = s2[0]; }
        __syncthreads();
        if (sg == 0) { s[0] += xs[o]; s2[0] += xs2[o]; }
    }
    if (sg == 0) {
        #pragma unroll
        for (int r = 0; r < REP; ++r) {
            g_part[(size_t)blockIdx.x*COUT*2 + (o + r*128)*2]     = s[r];
            g_part[(size_t)blockIdx.x*COUT*2 + (o + r*128)*2 + 1] = s2[r];
        }
    }
}

// ---------------- final 512->1024 GEMM (tf32 MMA, BN inline in staging) -----
__device__ __forceinline__ int fkey(float f) {
    int b = __float_as_int(f);
    return b >= 0 ? b : (b ^ 0x7FFFFFFF);
}

__global__ void out_init(int* ok) {
    ok[blockIdx.x*256 + threadIdx.x] = fkey(-CUDART_INF_F);
}

__device__ __forceinline__ unsigned cvt_tf32(float x) {
    unsigned u;
    asm("cvt.rna.tf32.f32 %0, %1;" : "=r"(u) : "f"(x));
    return u;
}
__device__ __forceinline__ float4 cvt4(float4 v) {
    v.x = __uint_as_float(cvt_tf32(v.x));
    v.y = __uint_as_float(cvt_tf32(v.y));
    v.z = __uint_as_float(cvt_tf32(v.z));
    v.w = __uint_as_float(cvt_tf32(v.w));
    return v;
}

#define AST  36
#define TILE (128*AST)
#define FSMEM_BYTES (4*TILE*4)

__global__ void __launch_bounds__(256, 1) final_kernel(const float* __restrict__ wf,
                                                       const float* __restrict__ bf,
                                                       int* __restrict__ okeys)
{
    extern __shared__ float smem_f[];
    float* sAb[2] = { smem_f,          smem_f + 2*TILE };
    float* sBb[2] = { smem_f + TILE,   smem_f + 3*TILE };
    __shared__ float sred[8][32];

    const int tid  = threadIdx.x;
    const int lane = tid & 31, w = tid >> 5;
    const int g = lane >> 2, tig = lane & 3;
    const int wm = w & 1, wn = w >> 1;
    const int b = blockIdx.z, n0 = blockIdx.x*128, o0 = blockIdx.y*128;
    const float* Ab = g_hcat + ((size_t)b*NN + n0)*CCAT;
    const float* Bw = wf + (size_t)o0*CCAT;

    float acc[4][4][4];
    #pragma unroll
    for (int mi = 0; mi < 4; ++mi)
        #pragma unroll
        for (int ni = 0; ni < 4; ++ni)
            #pragma unroll
            for (int j = 0; j < 4; ++j) acc[mi][ni][j] = 0.f;

    const int srow = tid >> 3;
    const int skq  = (tid & 7) * 4;

    float4 ra[4], rb[4];
    #define LDTILE(k0)                                                              \
        { _Pragma("unroll") for (int it = 0; it < 4; ++it)                          \
            ra[it] = *reinterpret_cast<const float4*>(                              \
                &Ab[(size_t)(srow + it*32)*CCAT + (k0) + skq]);                     \
          _Pragma("unroll") for (int it = 0; it < 4; ++it)                          \
            rb[it] = *reinterpret_cast<const float4*>(                              \
                &Bw[(size_t)(srow + it*32)*CCAT + (k0) + skq]); }
    // A tile gets BN+LeakyReLU inline (raw g_hcat -> normalized activations).
    // Macro-hygiene: all locals use _st_ prefix; buf/k0 must be simple names.
    #define STTILE(bufi, k0v)                                                       \
        { const int _st_ck = (k0v) + skq;                                           \
          const float _st_mu0 = g_mean[_st_ck],   _st_mu1 = g_mean[_st_ck+1],       \
                      _st_mu2 = g_mean[_st_ck+2], _st_mu3 = g_mean[_st_ck+3];       \
          const float _st_rr0 = g_rstd[_st_ck],   _st_rr1 = g_rstd[_st_ck+1],       \
                      _st_rr2 = g_rstd[_st_ck+2], _st_rr3 = g_rstd[_st_ck+3];       \
          _Pragma("unroll") for (int _st_it = 0; _st_it < 4; ++_st_it) {            \
            float4 _st_v = ra[_st_it];                                              \
            _st_v.x = bnl(_st_v.x, _st_mu0, _st_rr0);                               \
            _st_v.y = bnl(_st_v.y, _st_mu1, _st_rr1);                               \
            _st_v.z = bnl(_st_v.z, _st_mu2, _st_rr2);                               \
            _st_v.w = bnl(_st_v.w, _st_mu3, _st_rr3);                               \
            *reinterpret_cast<float4*>(                                             \
                &sAb[bufi][(srow + _st_it*32)*AST + skq]) = cvt4(_st_v); }          \
          _Pragma("unroll") for (int _st_it = 0; _st_it < 4; ++_st_it)              \
            *reinterpret_cast<float4*>(                                             \
                &sBb[bufi][(srow + _st_it*32)*AST + skq]) = cvt4(rb[_st_it]); }

    LDTILE(0); STTILE(0, 0);
    __syncthreads();

    for (int t = 0; t < 16; ++t) {
        const int cur = t & 1;
        const int nxt = (t + 1) & 1;
        const int nk0 = (t + 1) * 32;
        if (t < 15) LDTILE(nk0);
        const float* cA = sAb[cur];
        const float* cB = sBb[cur];
        #pragma unroll
        for (int k8 = 0; k8 < 4; ++k8) {
            const int kk = k8*8;
            unsigned a0[4], a1[4], a2[4], a3[4];
            #pragma unroll
            for (int mi = 0; mi < 4; ++mi) {
                int r = wm*64 + mi*16 + g;
                a0[mi] = __float_as_uint(cA[r*AST     + kk + tig]);
                a1[mi] = __float_as_uint(cA[(r+8)*AST + kk + tig]);
                a2[mi] = __float_as_uint(cA[r*AST     + kk + tig + 4]);
                a3[mi] = __float_as_uint(cA[(r+8)*AST + kk + tig + 4]);
            }
            unsigned b0[4], b1[4];
            #pragma unroll
            for (int ni = 0; ni < 4; ++ni) {
                int c = wn*32 + ni*8 + g;
                b0[ni] = __float_as_uint(cB[c*AST + kk + tig]);
                b1[ni] = __float_as_uint(cB[c*AST + kk + tig + 4]);
            }
            #pragma unroll
            for (int mi = 0; mi < 4; ++mi)
                #pragma unroll
                for (int ni = 0; ni < 4; ++ni) {
                    float* c = acc[mi][ni];
                    asm("mma.sync.aligned.m16n8k8.row.col.f32.tf32.tf32.f32 "
                        "{%0,%1,%2,%3}, {%4,%5,%6,%7}, {%8,%9}, {%0,%1,%2,%3};"
                        : "+f"(c[0]), "+f"(c[1]), "+f"(c[2]), "+f"(c[3])
                        : "r"(a0[mi]), "r"(a1[mi]), "r"(a2[mi]), "r"(a3[mi]),
                          "r"(b0[ni]), "r"(b1[ni]));
                }
        }
        if (t < 15) STTILE(nxt, nk0);
        __syncthreads();
    }

    #pragma unroll
    for (int ni = 0; ni < 4; ++ni) {
        float m0 = -CUDART_INF_F, m1 = -CUDART_INF_F;
        #pragma unroll
        for (int mi = 0; mi < 4; ++mi) {
            m0 = fmaxf(m0, fmaxf(acc[mi][ni][0], acc[mi][ni][2]));
            m1 = fmaxf(m1, fmaxf(acc[mi][ni][1], acc[mi][ni][3]));
        }
        #pragma unroll
        for (int sh = 4; sh <= 16; sh <<= 1) {
            m0 = fmaxf(m0, __shfl_xor_sync(0xffffffffu, m0, sh));
            m1 = fmaxf(m1, __shfl_xor_sync(0xffffffffu, m1, sh));
        }
        if (g == 0) {
            sred[w][ni*8 + tig*2]     = m0;
            sred[w][ni*8 + tig*2 + 1] = m1;
        }
    }
    __syncthreads();
    if (tid < 128) {
        int cwn = tid >> 5, c = tid & 31;
        float m = fmaxf(sred[cwn*2][c], sred[cwn*2+1][c]);
        int oc = o0 + cwn*32 + c;
        m += bf[oc];
        atomicMax(&okeys[b*1024 + oc], fkey(m));
    }
}

__global__ void out_convert(int* ok, float* out) {
    int i = blockIdx.x*256 + threadIdx.x;
    int k = ok[i];
    int bits = k >= 0 ? k : (k ^ 0x7FFFFFFF);
    out[i] = __int_as_float(bits);
}

// ---------------- launch ----------------------------------------------------
extern "C" void kernel_launch(void* const* d_in, const int* in_sizes, int n_in,
                              void* d_out, int out_size)
{
    const float* x      = (const float*)d_in[0];
    const float* w_edge = (const float*)d_in[1];
    const float* w1     = (const float*)d_in[3];
    const float* w2     = (const float*)d_in[5];
    const float* w3     = (const float*)d_in[7];
    const float* wf     = (const float*)d_in[9];
    const float* bf     = (const float*)d_in[10];

    cudaFuncSetAttribute(final_kernel,
                         cudaFuncAttributeMaxDynamicSharedMemorySize, FSMEM_BYTES);

    // launch order puts edge_kernel at the captured slot (4th launch)
    knn_kernel<<<dim3(NN/128, BB), 128>>>(x);
    out_init<<<out_size/256, 256>>>((int*)d_out);
    nop_kernel<<<1, 32>>>();

    edge_kernel<<<NBLK, 128>>>(x, w_edge);
    stats_kernel<<<64, 256>>>(64, 0, 1.f/(float)(BN*KNB));

    layer_kernel<64,64><<<NBLK, 128>>>(w1, 0, 64);
    stats_kernel<<<64, 256>>>(64, 64, 1.f/(float)BN);

    layer_kernel<64,128><<<NBLK, 128>>>(w2, 64, 128);
    stats_kernel<<<128, 256>>>(128, 128, 1.f/(float)BN);

    layer_kernel<128,256><<<NBLK, 128>>>(w3, 128, 256);
    stats_kernel<<<256, 256>>>(256, 256, 1.f/(float)BN);

    final_kernel<<<dim3(16, 8, 16), 256, FSMEM_BYTES>>>(wf, bf, (int*)d_out);
    out_convert<<<out_size/256, 256>>>((int*)d_out, (float*)d_out);
}

// round 15
// speedup vs baseline: 1.1778x; 1.1607x over previous
#include <cuda_runtime.h>
#include <math_constants.h>

#define BB   16
#define NN   2048
#define KNB  20
#define BN   (BB*NN)        // 32768
#define PTS  32
#define NBLK (BN/PTS)       // 1024
#define CCAT 512

// ---------------- scratch (device globals; no allocation allowed) ----------
__device__ int   g_idx [BN*KNB];
__device__ float g_hcat[BN*CCAT];
__device__ float g_pre [BN*256];
__device__ float g_part[NBLK*256*2];
__device__ float g_mean[256];
__device__ float g_rstd[256];

__global__ void nop_kernel() {}

// ---------------- kNN: EXACT top-20 (known-good R8 version) -----------------
__global__ void __launch_bounds__(128) knn_kernel(const float* __restrict__ x)
{
    __shared__ float4 sp[NN];                // (x, y, z, |p|^2)
    const int b = blockIdx.y;
    const float* xb = x + (size_t)b*NN*3;
    for (int i = threadIdx.x; i < NN; i += 128) {
        float a0 = xb[i*3], a1 = xb[i*3+1], a2 = xb[i*3+2];
        sp[i] = make_float4(a0, a1, a2, a0*a0 + a1*a1 + a2*a2);
    }
    __syncthreads();
    const int n = blockIdx.x*128 + threadIdx.x;
    const float4 q = sp[n];

    float bv[KNB]; int bi[KNB];
    #pragma unroll
    for (int j = 0; j < KNB; ++j) { bv[j] = -CUDART_INF_F; bi[j] = 0; }

    #pragma unroll 4
    for (int m = 0; m < NN; ++m) {
        float4 pm = sp[m];                   // broadcast LDS.128
        float v = 2.f*(q.x*pm.x + q.y*pm.y + q.z*pm.z) - q.w - pm.w;
        if (v > bv[KNB-1]) {
            #pragma unroll
            for (int j = KNB-1; j >= 1; --j) {
                bool shift = v > bv[j-1];
                float nv = shift ? bv[j-1] : v;
                int   ni = shift ? bi[j-1] : m;
                if (v > bv[j]) { bv[j] = nv; bi[j] = ni; }
            }
            if (v > bv[0]) { bv[0] = v; bi[0] = m; }
        }
    }
    int* out = g_idx + ((size_t)b*NN + n)*KNB;
    #pragma unroll
    for (int j = 0; j < KNB; ++j) out[j] = bi[j];
}

// ---------------- EdgeConv: pre-BN max over k + BN partials (128 threads) ---
__global__ void __launch_bounds__(128) edge_kernel(const float* __restrict__ x,
                                                   const float* __restrict__ w_edge)
{
    __shared__ float s_nb[PTS][KNB][3];
    __shared__ float s_ctr[PTS][3];
    __shared__ float xs[64], xs2[64];
    const int p0 = blockIdx.x * PTS;
    const int tid = threadIdx.x;

    for (int j = tid; j < PTS*KNB; j += 128) {
        int p = j / KNB, k = j - p*KNB;
        int gp = p0 + p;
        int bb = gp >> 11;
        int gi = g_idx[gp*KNB + k];
        const float* xp = x + ((size_t)bb*NN + gi)*3;
        s_nb[p][k][0] = xp[0]; s_nb[p][k][1] = xp[1]; s_nb[p][k][2] = xp[2];
    }
    if (tid < PTS) {
        int gp = p0 + tid;
        s_ctr[tid][0] = x[gp*3]; s_ctr[tid][1] = x[gp*3+1]; s_ctr[tid][2] = x[gp*3+2];
    }
    __syncthreads();

    const int o = tid & 63;
    const int sg = tid >> 6;                 // 0 or 1
    const float w0 = w_edge[o*6+0], w1 = w_edge[o*6+1], w2 = w_edge[o*6+2];
    const float w3 = w_edge[o*6+3], w4 = w_edge[o*6+4], w5 = w_edge[o*6+5];
    float s = 0.f, s2 = 0.f;
    const int pb = sg*16;
    for (int p = pb; p < pb+16; ++p) {
        float c0 = s_ctr[p][0], c1 = s_ctr[p][1], c2 = s_ctr[p][2];
        float base = w3*c0 + w4*c1 + w5*c2;
        float mx = -CUDART_INF_F;
        #pragma unroll
        for (int k = 0; k < KNB; ++k) {
            float v = base + w0*(s_nb[p][k][0]-c0)
                           + w1*(s_nb[p][k][1]-c1)
                           + w2*(s_nb[p][k][2]-c2);
            mx = fmaxf(mx, v);
            s += v; s2 += v*v;
        }
        g_pre[(size_t)(p0+p)*64 + o] = mx;
    }
    if (sg == 1) { xs[o] = s; xs2[o] = s2; }
    __syncthreads();
    if (sg == 0) {
        g_part[(size_t)blockIdx.x*128 + o*2]     = s  + xs[o];
        g_part[(size_t)blockIdx.x*128 + o*2 + 1] = s2 + xs2[o];
    }
}

// ---------------- BN statistics finalize (1 block per channel) --------------
__global__ void __launch_bounds__(256) stats_kernel(int O, float inv_count)
{
    __shared__ float rs[256], rs2[256];
    const int o = blockIdx.x;
    const int t = threadIdx.x;
    float s = 0.f, s2 = 0.f;
    for (int bk = t; bk < NBLK; bk += 256) {
        s  += g_part[(size_t)bk*O*2 + o*2];
        s2 += g_part[(size_t)bk*O*2 + o*2 + 1];
    }
    rs[t] = s; rs2[t] = s2;
    __syncthreads();
    for (int w = 128; w >= 1; w >>= 1) {
        if (t < w) { rs[t] += rs[t+w]; rs2[t] += rs2[t+w]; }
        __syncthreads();
    }
    if (t == 0) {
        float m   = rs[0]  * inv_count;
        float var = rs2[0] * inv_count - m*m;
        g_mean[o] = m;
        g_rstd[o] = rsqrtf(var + 1e-5f);
    }
}

// ---------------- BN + LeakyReLU apply (vectorized x4) ----------------------
__global__ void __launch_bounds__(256) apply_kernel(int O, int off)
{
    int i4 = blockIdx.x*256 + threadIdx.x;
    int i = i4*4;
    int p = i / O, o = i - p*O;
    float4 v = *reinterpret_cast<const float4*>(&g_pre[i]);
    v.x = (v.x - g_mean[o  ]) * g_rstd[o  ];
    v.y = (v.y - g_mean[o+1]) * g_rstd[o+1];
    v.z = (v.z - g_mean[o+2]) * g_rstd[o+2];
    v.w = (v.w - g_mean[o+3]) * g_rstd[o+3];
    v.x = v.x > 0.f ? v.x : 0.2f*v.x;
    v.y = v.y > 0.f ? v.y : 0.2f*v.y;
    v.z = v.z > 0.f ? v.z : 0.2f*v.z;
    v.w = v.w > 0.f ? v.w : 0.2f*v.w;
    *reinterpret_cast<float4*>(&g_hcat[(size_t)p*CCAT + off + o]) = v;
}

// ---------------- graph-max-pool gather + 1x1 conv + BN partials ------------
template<int CIN, int COUT>
__global__ void __launch_bounds__(128) layer_kernel(const float* __restrict__ w, int off_in)
{
    __shared__ float s_g[PTS*CIN];
    __shared__ int   s_idx[PTS*KNB];
    __shared__ float xs[128], xs2[128];
    const int tid = threadIdx.x;
    const int p0  = blockIdx.x * PTS;
    constexpr int C8 = CIN/8;

    for (int j = tid; j < PTS*KNB; j += 128) s_idx[j] = g_idx[(size_t)p0*KNB + j];
    __syncthreads();

    for (int v8 = tid; v8 < PTS*C8; v8 += 128) {
        int p = v8 / C8, c8 = (v8 - p*C8)*8;
        int gp = p0 + p, bb = gp >> 11;
        const float4* hb = reinterpret_cast<const float4*>(
            g_hcat + (size_t)bb*NN*CCAT + off_in + c8);
        float4 m0 = make_float4(-CUDART_INF_F,-CUDART_INF_F,-CUDART_INF_F,-CUDART_INF_F);
        float4 m1 = m0;
        #pragma unroll
        for (int j = 0; j < KNB; ++j) {
            size_t base = (size_t)s_idx[p*KNB+j]*(CCAT/4);
            float4 t0 = hb[base], t1 = hb[base+1];
            m0.x = fmaxf(m0.x, t0.x); m0.y = fmaxf(m0.y, t0.y);
            m0.z = fmaxf(m0.z, t0.z); m0.w = fmaxf(m0.w, t0.w);
            m1.x = fmaxf(m1.x, t1.x); m1.y = fmaxf(m1.y, t1.y);
            m1.z = fmaxf(m1.z, t1.z); m1.w = fmaxf(m1.w, t1.w);
        }
        *reinterpret_cast<float4*>(&s_g[p*CIN + c8])     = m0;
        *reinterpret_cast<float4*>(&s_g[p*CIN + c8 + 4]) = m1;
    }
    __syncthreads();

    constexpr int REP  = (COUT + 127)/128;
    constexpr int SEG  = (COUT >= 128) ? 1 : (128/COUT);
    constexpr int PSEG = PTS/SEG;
    const int o  = (COUT >= 128) ? tid : (tid & (COUT-1));
    const int sg = (COUT >= 128) ? 0   : (tid / COUT);
    const int pb = sg * PSEG;

    float acc[REP][PSEG];
    #pragma unroll
    for (int r = 0; r < REP; ++r)
        #pragma unroll
        for (int p = 0; p < PSEG; ++p) acc[r][p] = 0.f;

    for (int c = 0; c < CIN; ++c) {
        float wv[REP];
        #pragma unroll
        for (int r = 0; r < REP; ++r) wv[r] = w[(o + r*128)*CIN + c];
        #pragma unroll
        for (int p = 0; p < PSEG; ++p) {
            float sv = s_g[(pb + p)*CIN + c];
            #pragma unroll
            for (int r = 0; r < REP; ++r) acc[r][p] += wv[r]*sv;
        }
    }

    float s[REP], s2[REP];
    #pragma unroll
    for (int r = 0; r < REP; ++r) {
        s[r] = 0.f; s2[r] = 0.f;
        #pragma unroll
        for (int p = 0; p < PSEG; ++p) {
            float vv = acc[r][p];
            g_pre[(size_t)(p0 + pb + p)*COUT + o + r*128] = vv;
            s[r] += vv; s2[r] += vv*vv;
        }
    }
    if (SEG == 2) {
        if (sg == 1) { xs[o] = s[0]; xs2[o] = s2[0]; }
        __syncthreads();
        if (sg == 0) { s[0] += xs[o]; s2[0] += xs2[o]; }
    }
    if (sg == 0) {
        #pragma unroll
        for (int r = 0; r < REP; ++r) {
            g_part[(size_t)blockIdx.x*COUT*2 + (o + r*128)*2]     = s[r];
            g_part[(size_t)blockIdx.x*COUT*2 + (o + r*128)*2 + 1] = s2[r];
        }
    }
}

// ---------------- final 512->1024 GEMM (tf32 MMA, proven o64 single-buffer) -
__device__ __forceinline__ int fkey(float f) {
    int b = __float_as_int(f);
    return b >= 0 ? b : (b ^ 0x7FFFFFFF);
}

__global__ void out_init(int* ok) {
    ok[blockIdx.x*256 + threadIdx.x] = fkey(-CUDART_INF_F);
}

__device__ __forceinline__ unsigned cvt_tf32(float x) {
    unsigned u;
    asm("cvt.rna.tf32.f32 %0, %1;" : "=r"(u) : "f"(x));
    return u;
}

#define AST 36   // smem row stride (floats): frag loads conflict-free

__global__ void __launch_bounds__(256) final_kernel(const float* __restrict__ wf,
                                                    const float* __restrict__ bf,
                                                    int* __restrict__ okeys)
{
    __shared__ float sA[128*AST];   // [row][k] A tile 128x32 (tf32-rounded)
    __shared__ float sB[64*AST];    // [o]  [k] B tile 64x32
    __shared__ float sred[8][16];

    const int tid  = threadIdx.x;
    const int lane = tid & 31, w = tid >> 5;
    const int g = lane >> 2, tig = lane & 3;
    const int wm = w & 1, wn = w >> 1;           // warp tile: 64 rows x 16 cols
    const int b = blockIdx.z, n0 = blockIdx.x*128, o0 = blockIdx.y*64;
    const float* Ab = g_hcat + ((size_t)b*NN + n0)*CCAT;
    const float* Bw = wf + (size_t)o0*CCAT;

    float acc[4][2][4];
    #pragma unroll
    for (int mi = 0; mi < 4; ++mi)
        #pragma unroll
        for (int ni = 0; ni < 2; ++ni)
            #pragma unroll
            for (int j = 0; j < 4; ++j) acc[mi][ni][j] = 0.f;

    const int srow = tid >> 3;        // 0..31
    const int skq  = (tid & 7) * 4;   // 0,4,...,28

    for (int k0 = 0; k0 < CCAT; k0 += 32) {
        // stage A (128x32) and B (64x32), rounding to tf32 once here
        #pragma unroll
        for (int it = 0; it < 4; ++it) {
            int r = srow + it*32;
            float4 v = *reinterpret_cast<const float4*>(&Ab[(size_t)r*CCAT + k0 + skq]);
            float* d = &sA[r*AST + skq];
            d[0] = __uint_as_float(cvt_tf32(v.x));
            d[1] = __uint_as_float(cvt_tf32(v.y));
            d[2] = __uint_as_float(cvt_tf32(v.z));
            d[3] = __uint_as_float(cvt_tf32(v.w));
        }
        #pragma unroll
        for (int it = 0; it < 2; ++it) {
            int r = srow + it*32;
            float4 v = *reinterpret_cast<const float4*>(&Bw[(size_t)r*CCAT + k0 + skq]);
            float* d = &sB[r*AST + skq];
            d[0] = __uint_as_float(cvt_tf32(v.x));
            d[1] = __uint_as_float(cvt_tf32(v.y));
            d[2] = __uint_as_float(cvt_tf32(v.z));
            d[3] = __uint_as_float(cvt_tf32(v.w));
        }
        __syncthreads();

        #pragma unroll
        for (int k8 = 0; k8 < 4; ++k8) {
            const int kk = k8*8;
            unsigned a0[4], a1[4], a2[4], a3[4];
            #pragma unroll
            for (int mi = 0; mi < 4; ++mi) {
                int r = wm*64 + mi*16 + g;
                a0[mi] = __float_as_uint(sA[r*AST      + kk + tig]);
                a1[mi] = __float_as_uint(sA[(r+8)*AST  + kk + tig]);
                a2[mi] = __float_as_uint(sA[r*AST      + kk + tig + 4]);
                a3[mi] = __float_as_uint(sA[(r+8)*AST  + kk + tig + 4]);
            }
            unsigned b0[2], b1[2];
            #pragma unroll
            for (int ni = 0; ni < 2; ++ni) {
                int c = wn*16 + ni*8 + g;
                b0[ni] = __float_as_uint(sB[c*AST + kk + tig]);
                b1[ni] = __float_as_uint(sB[c*AST + kk + tig + 4]);
            }
            #pragma unroll
            for (int mi = 0; mi < 4; ++mi)
                #pragma unroll
                for (int ni = 0; ni < 2; ++ni) {
                    float* c = acc[mi][ni];
                    asm("mma.sync.aligned.m16n8k8.row.col.f32.tf32.tf32.f32 "
                        "{%0,%1,%2,%3}, {%4,%5,%6,%7}, {%8,%9}, {%0,%1,%2,%3};"
                        : "+f"(c[0]), "+f"(c[1]), "+f"(c[2]), "+f"(c[3])
                        : "r"(a0[mi]), "r"(a1[mi]), "r"(a2[mi]), "r"(a3[mi]),
                          "r"(b0[ni]), "r"(b1[ni]));
                }
        }
        __syncthreads();
    }

    // ---- max over the 128 rows of this block's tile ----
    #pragma unroll
    for (int ni = 0; ni < 2; ++ni) {
        float m0 = -CUDART_INF_F, m1 = -CUDART_INF_F;
        #pragma unroll
        for (int mi = 0; mi < 4; ++mi) {
            m0 = fmaxf(m0, fmaxf(acc[mi][ni][0], acc[mi][ni][2]));
            m1 = fmaxf(m1, fmaxf(acc[mi][ni][1], acc[mi][ni][3]));
        }
        #pragma unroll
        for (int sh = 4; sh <= 16; sh <<= 1) {
            m0 = fmaxf(m0, __shfl_xor_sync(0xffffffffu, m0, sh));
            m1 = fmaxf(m1, __shfl_xor_sync(0xffffffffu, m1, sh));
        }
        if (g == 0) {
            sred[w][ni*8 + tig*2]     = m0;
            sred[w][ni*8 + tig*2 + 1] = m1;
        }
    }
    __syncthreads();
    if (tid < 64) {
        int cwn = tid >> 4, c16 = tid & 15;
        float m = fmaxf(sred[cwn*2][c16], sred[cwn*2+1][c16]);
        int oc = o0 + cwn*16 + c16;
        m += bf[oc];                      // bias commutes with max over n
        atomicMax(&okeys[b*1024 + oc], fkey(m));
    }
}

__global__ void out_convert(int* ok, float* out) {
    int i = blockIdx.x*256 + threadIdx.x;
    int k = ok[i];
    int bits = k >= 0 ? k : (k ^ 0x7FFFFFFF);
    out[i] = __int_as_float(bits);
}

// ---------------- launch ----------------------------------------------------
extern "C" void kernel_launch(void* const* d_in, const int* in_sizes, int n_in,
                              void* d_out, int out_size)
{
    const float* x      = (const float*)d_in[0];
    const float* w_edge = (const float*)d_in[1];
    const float* w1     = (const float*)d_in[3];
    const float* w2     = (const float*)d_in[5];
    const float* w3     = (const float*)d_in[7];
    const float* wf     = (const float*)d_in[9];
    const float* bf     = (const float*)d_in[10];

    // slots 0-2 are fillers so the ncu capture (launch index 3) hits knn
    out_init<<<out_size/256, 256>>>((int*)d_out);
    nop_kernel<<<1, 32>>>();
    nop_kernel<<<1, 32>>>();

    knn_kernel<<<dim3(NN/128, BB), 128>>>(x);

    edge_kernel<<<NBLK, 128>>>(x, w_edge);
    stats_kernel<<<64, 256>>>(64, 1.f/(float)(BN*KNB));
    apply_kernel<<<BN*64/1024, 256>>>(64, 0);

    layer_kernel<64,64><<<NBLK, 128>>>(w1, 0);
    stats_kernel<<<64, 256>>>(64, 1.f/(float)BN);
    apply_kernel<<<BN*64/1024, 256>>>(64, 64);

    layer_kernel<64,128><<<NBLK, 128>>>(w2, 64);
    stats_kernel<<<128, 256>>>(128, 1.f/(float)BN);
    apply_kernel<<<BN*128/1024, 256>>>(128, 128);

    layer_kernel<128,256><<<NBLK, 128>>>(w3, 128);
    stats_kernel<<<256, 256>>>(256, 1.f/(float)BN);
    apply_kernel<<<BN*256/1024, 256>>>(256, 256);

    final_kernel<<<dim3(16, 16, 16), 256>>>(wf, bf, (int*)d_out);
    out_convert<<<out_size/256, 256>>>((int*)d_out, (float*)d_out);
}